// round 13
// baseline (speedup 1.0000x reference)
#include <cuda_runtime.h>
#include <cuda_fp16.h>
#include <stdint.h>

#define B_  8
#define T_  2048
#define E_  1024
#define H_  128
#define BT_ (B_*T_)
#define NSPLIT 4

// ---- global scratch ----
__device__ __half gw[3][E_*H_];
__device__ __half gq[BT_*H_];
__device__ __half gk[BT_*H_];
__device__ __half gv[BT_*H_];
__device__ __half goh[NSPLIT][BT_*H_];  // normalized partial O (fp16)
__device__ float  gm[NSPLIT][BT_];      // partial row max
__device__ float  gl[NSPLIT][BT_];      // partial row sum

// ---- helpers ----
__device__ __forceinline__ void ldm_x4(uint32_t* r, const void* p) {
    uint32_t a = (uint32_t)__cvta_generic_to_shared(p);
    asm volatile("ldmatrix.sync.aligned.m8n8.x4.shared.b16 {%0,%1,%2,%3}, [%4];"
                 : "=r"(r[0]), "=r"(r[1]), "=r"(r[2]), "=r"(r[3]) : "r"(a));
}
__device__ __forceinline__ void ldm_x4_t(uint32_t* r, const void* p) {
    uint32_t a = (uint32_t)__cvta_generic_to_shared(p);
    asm volatile("ldmatrix.sync.aligned.m8n8.x4.trans.shared.b16 {%0,%1,%2,%3}, [%4];"
                 : "=r"(r[0]), "=r"(r[1]), "=r"(r[2]), "=r"(r[3]) : "r"(a));
}
__device__ __forceinline__ void mma16816(float* d, const uint32_t* a, const uint32_t* b) {
    asm volatile("mma.sync.aligned.m16n8k16.row.col.f32.f16.f16.f32 "
                 "{%0,%1,%2,%3}, {%4,%5,%6,%7}, {%8,%9}, {%0,%1,%2,%3};"
                 : "+f"(d[0]), "+f"(d[1]), "+f"(d[2]), "+f"(d[3])
                 : "r"(a[0]), "r"(a[1]), "r"(a[2]), "r"(a[3]), "r"(b[0]), "r"(b[1]));
}
__device__ __forceinline__ uint32_t pack_h2(float a, float b) {
    __half2 h;
    h.x = __float2half_rn(a);
    h.y = __float2half_rn(b);
    return *reinterpret_cast<uint32_t*>(&h);
}
__device__ __forceinline__ void cp16(void* smem, const void* gmem) {
    uint32_t a = (uint32_t)__cvta_generic_to_shared(smem);
    asm volatile("cp.async.cg.shared.global [%0], [%1], 16;" :: "r"(a), "l"(gmem));
}
__device__ __forceinline__ void cp_commit() { asm volatile("cp.async.commit_group;"); }
template<int N> __device__ __forceinline__ void cp_wait() {
    asm volatile("cp.async.wait_group %0;" :: "n"(N));
}

// ---------------------------------------------------------------------------
// Convert W: fp32 -> fp16 (tiny: 1.5 MB)
// ---------------------------------------------------------------------------
__global__ void conv_w_kernel(const float* __restrict__ Wq,
                              const float* __restrict__ Wk,
                              const float* __restrict__ Wv)
{
    const float* W = (blockIdx.y == 0) ? Wq : (blockIdx.y == 1) ? Wk : Wv;
    __half* o = gw[blockIdx.y];
    int i = blockIdx.x * 256 + threadIdx.x;
    float4 v = reinterpret_cast<const float4*>(W)[i];
    uint2 hv;
    hv.x = pack_h2(v.x, v.y);
    hv.y = pack_h2(v.z, v.w);
    reinterpret_cast<uint2*>(o)[i] = hv;
}

// ---------------------------------------------------------------------------
// Projection: 128x128 CTA tile, 8 warps, BK=64, fp16 MMA.
// X: read fp32 directly from input, convert, STS (double buffered).
// W: 2-stage cp.async.
// ---------------------------------------------------------------------------
#define PX_ (128*72)
#define PW_ (64*136)

__global__ __launch_bounds__(256, 2) void proj_mma(const float* __restrict__ x)
{
    extern __shared__ __half smp[];
    __half* Xs = smp;               // [2][128*72] fp16
    __half* Ws = Xs + 2*PX_;        // [2][64*136]

    const int mat = blockIdx.y;
    const __half* wp = gw[mat];
    __half* op = (mat == 0) ? gq : (mat == 1) ? gk : gv;

    const int r0   = blockIdx.x * 128;
    const int tid  = threadIdx.x;
    const int wrp  = tid >> 5;
    const int lane = tid & 31;
    const int mw   = wrp & 3;
    const int nw   = wrp >> 2;
    const int g    = lane >> 2;
    const int tg   = lane & 3;

    // X: 128 rows x 64 cols fp32 -> fp16 smem. 16 float4 per row; 8 per thread.
    auto load_x = [&](int kc, int s) {
        const int k0 = kc * 64;
        #pragma unroll
        for (int it = 0; it < 8; it++) {
            int idx = it*256 + tid;
            int row = idx >> 4, u = idx & 15;
            float4 v = *reinterpret_cast<const float4*>(x + (size_t)(r0 + row) * E_ + k0 + u*4);
            uint2 hv;
            hv.x = pack_h2(v.x, v.y);
            hv.y = pack_h2(v.z, v.w);
            *reinterpret_cast<uint2*>(Xs + s*PX_ + row*72 + u*4) = hv;
        }
    };
    auto issue_w = [&](int kc, int s) {
        const int k0 = kc * 64;
        #pragma unroll
        for (int it = 0; it < 4; it++) {
            int idx = it*256 + tid;
            int row = idx >> 4, u = idx & 15;
            cp16(Ws + s*PW_ + row*136 + u*8, wp + (size_t)(k0 + row) * H_ + u*8);
        }
        cp_commit();
    };

    float acc[2][8][4];
    #pragma unroll
    for (int mf = 0; mf < 2; mf++)
        #pragma unroll
        for (int f = 0; f < 8; f++)
            #pragma unroll
            for (int e = 0; e < 4; e++) acc[mf][f][e] = 0.f;

    issue_w(0, 0);
    load_x(0, 0);

    for (int kc = 0; kc < 16; kc++) {
        const int s = kc & 1;
        if (kc < 15) {
            issue_w(kc+1, s^1);
            cp_wait<1>();
            load_x(kc+1, s^1);
        } else {
            cp_wait<0>();
        }
        __syncthreads();

        const __half* xs = Xs + s*PX_;
        const __half* ws = Ws + s*PW_;

        #pragma unroll
        for (int kk = 0; kk < 4; kk++) {
            uint32_t a[2][4];
            #pragma unroll
            for (int mf = 0; mf < 2; mf++) {
                const int arow = mw*32 + mf*16 + (lane & 15);
                const int acol = kk*16 + (lane >> 4) * 8;
                ldm_x4(a[mf], xs + arow*72 + acol);
            }
            const int brow = kk*16 + (lane & 7) + ((lane >> 3) & 1) * 8;
            #pragma unroll
            for (int fp = 0; fp < 4; fp++) {
                uint32_t bb[4];
                const int bcol = nw*64 + fp*16 + ((lane >> 4) & 1) * 8;
                ldm_x4_t(bb, ws + brow*136 + bcol);
                #pragma unroll
                for (int mf = 0; mf < 2; mf++) {
                    mma16816(acc[mf][2*fp],   a[mf], &bb[0]);
                    mma16816(acc[mf][2*fp+1], a[mf], &bb[2]);
                }
            }
        }
        __syncthreads();
    }

    const float scale = (mat == 0) ? 0.08838834764831845f : 1.0f;
    #pragma unroll
    for (int mf = 0; mf < 2; mf++) {
        const int row0 = r0 + mw*32 + mf*16 + g;
        const int row1 = row0 + 8;
        #pragma unroll
        for (int f = 0; f < 8; f++) {
            const int col = nw*64 + f*8 + tg*2;
            *reinterpret_cast<uint32_t*>(op + (size_t)row0*H_ + col) =
                pack_h2(acc[mf][f][0]*scale, acc[mf][f][1]*scale);
            *reinterpret_cast<uint32_t*>(op + (size_t)row1*H_ + col) =
                pack_h2(acc[mf][f][2]*scale, acc[mf][f][3]*scale);
        }
    }
}

// ---------------------------------------------------------------------------
// Flash attention, split-KV(4): grid (4*T/64, B). Writes normalized fp16
// partial O plus (m, l) per row.
// ---------------------------------------------------------------------------
#define AT_ (64*136)

__global__ __launch_bounds__(128, 2) void attn_mma()
{
    extern __shared__ __half sma[];
    __half* Qs = sma;              // [64*136]
    __half* Ks = Qs + AT_;         // [2][64*136]
    __half* Vs = Ks + 2*AT_;       // [2][64*136]

    const int b    = blockIdx.y;
    const int nq   = (int)gridDim.x / NSPLIT;
    const int qi   = nq - 1 - ((int)blockIdx.x / NSPLIT);   // longest first
    const int p    = blockIdx.x % NSPLIT;
    const int q0   = qi * 64;
    const int ntile = qi + 1;
    const int j0   = (ntile * p) / NSPLIT;
    const int j1   = (ntile * (p + 1)) / NSPLIT;
    const int tid  = threadIdx.x;
    const int wrp  = tid >> 5;
    const int lane = tid & 31;
    const int g    = lane >> 2;
    const int tg   = lane & 3;

    float o[16][4];
    #pragma unroll
    for (int f = 0; f < 16; f++)
        #pragma unroll
        for (int e = 0; e < 4; e++) o[f][e] = 0.f;
    float m0 = -1e30f, m1 = -1e30f, l0 = 0.f, l1 = 0.f;

    auto issue_kv = [&](int j, int s) {
        const __half* kp = gk + (size_t)(b*T_ + j*64) * H_;
        const __half* vp = gv + (size_t)(b*T_ + j*64) * H_;
        #pragma unroll
        for (int it = 0; it < 8; it++) {
            int idx = it*128 + tid;
            int row = idx >> 4, u = idx & 15;
            int d = row*136 + u*8;
            size_t src = (size_t)row*H_ + u*8;
            cp16(Ks + s*AT_ + d, kp + src);
            cp16(Vs + s*AT_ + d, vp + src);
        }
        cp_commit();
    };

    if (j1 > j0) {
        // prologue: Q + KV stage j0
        {
            const __half* qp = gq + (size_t)(b*T_ + q0) * H_;
            #pragma unroll
            for (int it = 0; it < 8; it++) {
                int idx = it*128 + tid;
                int row = idx >> 4, u = idx & 15;
                cp16(Qs + row*136 + u*8, qp + (size_t)row*H_ + u*8);
            }
            const __half* kp = gk + (size_t)(b*T_ + j0*64) * H_;
            const __half* vp = gv + (size_t)(b*T_ + j0*64) * H_;
            #pragma unroll
            for (int it = 0; it < 8; it++) {
                int idx = it*128 + tid;
                int row = idx >> 4, u = idx & 15;
                int d = row*136 + u*8;
                size_t src = (size_t)row*H_ + u*8;
                cp16(Ks + d, kp + src);
                cp16(Vs + d, vp + src);
            }
            cp_commit();
        }

        for (int j = j0; j < j1; j++) {
            const int s = (j - j0) & 1;
            if (j + 1 < j1) { issue_kv(j+1, s^1); cp_wait<1>(); }
            else            { cp_wait<0>(); }
            __syncthreads();

            const __half* ks = Ks + s*AT_;
            const __half* vs = Vs + s*AT_;

            // ---- S = Q @ K^T ----
            float sv[8][4];
            #pragma unroll
            for (int f = 0; f < 8; f++)
                #pragma unroll
                for (int e = 0; e < 4; e++) sv[f][e] = 0.f;

            #pragma unroll
            for (int kk = 0; kk < 8; kk++) {
                uint32_t a[4];
                const int arow = 16*wrp + (lane & 15);
                const int acol = kk*16 + (lane >> 4) * 8;
                ldm_x4(a, Qs + arow*136 + acol);
                #pragma unroll
                for (int fp = 0; fp < 4; fp++) {
                    uint32_t bb[4];
                    const int brow = fp*16 + (lane & 7) + ((lane >> 4) & 1) * 8;
                    const int bcol = kk*16 + ((lane >> 3) & 1) * 8;
                    ldm_x4(bb, ks + brow*136 + bcol);
                    mma16816(sv[2*fp],   a, &bb[0]);
                    mma16816(sv[2*fp+1], a, &bb[2]);
                }
            }

            // ---- causal mask (diagonal tile) ----
            if (j == qi) {
                #pragma unroll
                for (int f = 0; f < 8; f++) {
                    #pragma unroll
                    for (int e = 0; e < 4; e++) {
                        int col = f*8 + tg*2 + (e & 1);
                        int row = wrp*16 + g + ((e >> 1) ? 8 : 0);
                        if (col > row) sv[f][e] = -1e30f;
                    }
                }
            }

            // ---- online softmax ----
            float rm0 = -1e30f, rm1 = -1e30f;
            #pragma unroll
            for (int f = 0; f < 8; f++) {
                rm0 = fmaxf(rm0, fmaxf(sv[f][0], sv[f][1]));
                rm1 = fmaxf(rm1, fmaxf(sv[f][2], sv[f][3]));
            }
            rm0 = fmaxf(rm0, __shfl_xor_sync(0xffffffffu, rm0, 1));
            rm0 = fmaxf(rm0, __shfl_xor_sync(0xffffffffu, rm0, 2));
            rm1 = fmaxf(rm1, __shfl_xor_sync(0xffffffffu, rm1, 1));
            rm1 = fmaxf(rm1, __shfl_xor_sync(0xffffffffu, rm1, 2));
            const float mn0 = fmaxf(m0, rm0), mn1 = fmaxf(m1, rm1);
            const float c0 = __expf(m0 - mn0), c1 = __expf(m1 - mn1);
            float ls0 = 0.f, ls1 = 0.f;
            #pragma unroll
            for (int f = 0; f < 8; f++) {
                sv[f][0] = __expf(sv[f][0] - mn0);
                sv[f][1] = __expf(sv[f][1] - mn0);
                sv[f][2] = __expf(sv[f][2] - mn1);
                sv[f][3] = __expf(sv[f][3] - mn1);
                ls0 += sv[f][0] + sv[f][1];
                ls1 += sv[f][2] + sv[f][3];
            }
            ls0 += __shfl_xor_sync(0xffffffffu, ls0, 1);
            ls0 += __shfl_xor_sync(0xffffffffu, ls0, 2);
            ls1 += __shfl_xor_sync(0xffffffffu, ls1, 1);
            ls1 += __shfl_xor_sync(0xffffffffu, ls1, 2);
            l0 = l0*c0 + ls0; l1 = l1*c1 + ls1;
            m0 = mn0; m1 = mn1;

            const bool noscale = (c0 == 1.0f) & (c1 == 1.0f);
            if (!__all_sync(0xffffffffu, noscale)) {
                #pragma unroll
                for (int f = 0; f < 16; f++) {
                    o[f][0] *= c0; o[f][1] *= c0;
                    o[f][2] *= c1; o[f][3] *= c1;
                }
            }

            // ---- O += P @ V ----
            #pragma unroll
            for (int kk = 0; kk < 4; kk++) {
                uint32_t a[4];
                a[0] = pack_h2(sv[2*kk][0],   sv[2*kk][1]);
                a[1] = pack_h2(sv[2*kk][2],   sv[2*kk][3]);
                a[2] = pack_h2(sv[2*kk+1][0], sv[2*kk+1][1]);
                a[3] = pack_h2(sv[2*kk+1][2], sv[2*kk+1][3]);
                const int brow = kk*16 + (lane & 7) + ((lane >> 3) & 1) * 8;
                #pragma unroll
                for (int fp = 0; fp < 8; fp++) {
                    uint32_t bb[4];
                    const int bcol = fp*16 + ((lane >> 4) & 1) * 8;
                    ldm_x4_t(bb, vs + brow*136 + bcol);
                    mma16816(o[2*fp],   a, &bb[0]);
                    mma16816(o[2*fp+1], a, &bb[2]);
                }
            }
            __syncthreads();
        }
    }

    // ---- epilogue: normalized fp16 partial O + (m, l) ----
    const float inv0 = (l0 > 0.f) ? 1.0f / l0 : 0.f;
    const float inv1 = (l1 > 0.f) ? 1.0f / l1 : 0.f;
    const size_t row0 = (size_t)b*T_ + q0 + wrp*16 + g;
    const size_t row1 = row0 + 8;
    __half* gop = goh[p];
    #pragma unroll
    for (int f = 0; f < 16; f++) {
        const int col = f*8 + tg*2;
        *reinterpret_cast<uint32_t*>(gop + row0*H_ + col) = pack_h2(o[f][0]*inv0, o[f][1]*inv0);
        *reinterpret_cast<uint32_t*>(gop + row1*H_ + col) = pack_h2(o[f][2]*inv1, o[f][3]*inv1);
    }
    if (tg == 0) {
        gm[p][row0] = m0; gl[p][row0] = l0;
        gm[p][row1] = m1; gl[p][row1] = l1;
    }
}

// ---------------------------------------------------------------------------
// Merge 4 normalized fp16 partials: out = sum_p w_p*Ohat_p / sum_p w_p,
// w_p = l_p * exp(m_p - m).
// ---------------------------------------------------------------------------
__global__ void merge_kernel(float* __restrict__ out)
{
    int i = blockIdx.x * 256 + threadIdx.x;     // float4 group over BT_*H_
    int row = i >> 5;
    float w[NSPLIT];
    float m = -1e30f;
    #pragma unroll
    for (int p = 0; p < NSPLIT; p++) m = fmaxf(m, gm[p][row]);
    float wsum = 0.f;
    #pragma unroll
    for (int p = 0; p < NSPLIT; p++) {
        w[p] = gl[p][row] * __expf(gm[p][row] - m);
        wsum += w[p];
    }
    float inv = 1.0f / wsum;
    float4 r = make_float4(0.f, 0.f, 0.f, 0.f);
    #pragma unroll
    for (int p = 0; p < NSPLIT; p++) {
        uint2 hv = reinterpret_cast<const uint2*>(goh[p])[i];
        __half2 h0 = *reinterpret_cast<__half2*>(&hv.x);
        __half2 h1 = *reinterpret_cast<__half2*>(&hv.y);
        float2 f0 = __half22float2(h0);
        float2 f1 = __half22float2(h1);
        r.x += f0.x * w[p];
        r.y += f0.y * w[p];
        r.z += f1.x * w[p];
        r.w += f1.y * w[p];
    }
    r.x *= inv; r.y *= inv; r.z *= inv; r.w *= inv;
    reinterpret_cast<float4*>(out)[i] = r;
}

extern "C" void kernel_launch(void* const* d_in, const int* in_sizes, int n_in,
                              void* d_out, int out_size)
{
    const float* x  = (const float*)d_in[0];
    const float* Wq = (const float*)d_in[1];
    const float* Wk = (const float*)d_in[2];
    const float* Wv = (const float*)d_in[3];
    float* out = (float*)d_out;

    const int proj_smem = (2*PX_ + 2*PW_) * (int)sizeof(__half);   // 71680
    const int attn_smem = 5*AT_ * (int)sizeof(__half);             // 87040
    cudaFuncSetAttribute(proj_mma, cudaFuncAttributeMaxDynamicSharedMemorySize, proj_smem);
    cudaFuncSetAttribute(attn_mma, cudaFuncAttributeMaxDynamicSharedMemorySize, attn_smem);

    conv_w_kernel<<<dim3(E_*H_/4/256, 3), 256>>>(Wq, Wk, Wv);
    proj_mma<<<dim3(BT_/128, 3), 256, proj_smem>>>(x);
    attn_mma<<<dim3(NSPLIT*T_/64, B_), 128, attn_smem>>>();
    merge_kernel<<<BT_*H_/4/256, 256>>>(out);
}

// round 14
// speedup vs baseline: 1.0414x; 1.0414x over previous
#include <cuda_runtime.h>
#include <cuda_fp16.h>
#include <stdint.h>

#define B_  8
#define T_  2048
#define E_  1024
#define H_  128
#define BT_ (B_*T_)
#define NSPLIT 4

// ---- global scratch ----
__device__ __half gx[BT_*E_];
__device__ __half gw[3][E_*H_];
__device__ __half gq[BT_*H_];
__device__ __half gk[BT_*H_];
__device__ __half gv[BT_*H_];
__device__ __half goh[NSPLIT][BT_*H_];  // normalized partial O (fp16)
__device__ float  gm[NSPLIT][BT_];      // partial row max
__device__ float  gl[NSPLIT][BT_];      // partial row sum

// ---- helpers ----
__device__ __forceinline__ void ldm_x4(uint32_t* r, const void* p) {
    uint32_t a = (uint32_t)__cvta_generic_to_shared(p);
    asm volatile("ldmatrix.sync.aligned.m8n8.x4.shared.b16 {%0,%1,%2,%3}, [%4];"
                 : "=r"(r[0]), "=r"(r[1]), "=r"(r[2]), "=r"(r[3]) : "r"(a));
}
__device__ __forceinline__ void ldm_x4_t(uint32_t* r, const void* p) {
    uint32_t a = (uint32_t)__cvta_generic_to_shared(p);
    asm volatile("ldmatrix.sync.aligned.m8n8.x4.trans.shared.b16 {%0,%1,%2,%3}, [%4];"
                 : "=r"(r[0]), "=r"(r[1]), "=r"(r[2]), "=r"(r[3]) : "r"(a));
}
__device__ __forceinline__ void mma16816(float* d, const uint32_t* a, const uint32_t* b) {
    asm volatile("mma.sync.aligned.m16n8k16.row.col.f32.f16.f16.f32 "
                 "{%0,%1,%2,%3}, {%4,%5,%6,%7}, {%8,%9}, {%0,%1,%2,%3};"
                 : "+f"(d[0]), "+f"(d[1]), "+f"(d[2]), "+f"(d[3])
                 : "r"(a[0]), "r"(a[1]), "r"(a[2]), "r"(a[3]), "r"(b[0]), "r"(b[1]));
}
__device__ __forceinline__ uint32_t pack_h2(float a, float b) {
    __half2 h;
    h.x = __float2half_rn(a);
    h.y = __float2half_rn(b);
    return *reinterpret_cast<uint32_t*>(&h);
}
__device__ __forceinline__ void cp16(void* smem, const void* gmem) {
    uint32_t a = (uint32_t)__cvta_generic_to_shared(smem);
    asm volatile("cp.async.cg.shared.global [%0], [%1], 16;" :: "r"(a), "l"(gmem));
}
__device__ __forceinline__ void cp_commit() { asm volatile("cp.async.commit_group;"); }
template<int N> __device__ __forceinline__ void cp_wait() {
    asm volatile("cp.async.wait_group %0;" :: "n"(N));
}

// ---------------------------------------------------------------------------
// Convert kernels: fp32 -> fp16
// ---------------------------------------------------------------------------
__global__ void conv_x_kernel(const float* __restrict__ x)
{
    int i = blockIdx.x * 256 + threadIdx.x;
    float4 v = reinterpret_cast<const float4*>(x)[i];
    uint2 hv;
    hv.x = pack_h2(v.x, v.y);
    hv.y = pack_h2(v.z, v.w);
    reinterpret_cast<uint2*>(gx)[i] = hv;
}

__global__ void conv_w_kernel(const float* __restrict__ Wq,
                              const float* __restrict__ Wk,
                              const float* __restrict__ Wv)
{
    const float* W = (blockIdx.y == 0) ? Wq : (blockIdx.y == 1) ? Wk : Wv;
    __half* o = gw[blockIdx.y];
    int i = blockIdx.x * 256 + threadIdx.x;
    float4 v = reinterpret_cast<const float4*>(W)[i];
    uint2 hv;
    hv.x = pack_h2(v.x, v.y);
    hv.y = pack_h2(v.z, v.w);
    reinterpret_cast<uint2*>(o)[i] = hv;
}

// ---------------------------------------------------------------------------
// Projection: 128x128 CTA tile, 8 warps (warp tile 32x64), BK=64,
// 2-stage cp.async (both X and W), fp16 MMA. 2 CTAs/SM.
// ---------------------------------------------------------------------------
#define PX_ (128*72)
#define PW_ (64*136)

__global__ __launch_bounds__(256, 2) void proj_mma()
{
    extern __shared__ __half smp[];
    __half* Xs = smp;               // [2][128*72]
    __half* Ws = Xs + 2*PX_;        // [2][64*136]

    const int mat = blockIdx.y;
    const __half* wp = gw[mat];
    __half* op = (mat == 0) ? gq : (mat == 1) ? gk : gv;

    const int r0   = blockIdx.x * 128;
    const int tid  = threadIdx.x;
    const int wrp  = tid >> 5;
    const int lane = tid & 31;
    const int mw   = wrp & 3;
    const int nw   = wrp >> 2;
    const int g    = lane >> 2;
    const int tg   = lane & 3;

    auto issue = [&](int kc, int s) {
        const int k0 = kc * 64;
        #pragma unroll
        for (int it = 0; it < 4; it++) {
            int idx = it*256 + tid;
            int row = idx >> 3, u = idx & 7;
            cp16(Xs + s*PX_ + row*72 + u*8, gx + (size_t)(r0 + row) * E_ + k0 + u*8);
        }
        #pragma unroll
        for (int it = 0; it < 4; it++) {
            int idx = it*256 + tid;
            int row = idx >> 4, u = idx & 15;
            cp16(Ws + s*PW_ + row*136 + u*8, wp + (size_t)(k0 + row) * H_ + u*8);
        }
        cp_commit();
    };

    float acc[2][8][4];
    #pragma unroll
    for (int mf = 0; mf < 2; mf++)
        #pragma unroll
        for (int f = 0; f < 8; f++)
            #pragma unroll
            for (int e = 0; e < 4; e++) acc[mf][f][e] = 0.f;

    issue(0, 0);

    for (int kc = 0; kc < 16; kc++) {
        const int s = kc & 1;
        if (kc < 15) { issue(kc+1, s^1); cp_wait<1>(); }
        else         { cp_wait<0>(); }
        __syncthreads();

        const __half* xs = Xs + s*PX_;
        const __half* ws = Ws + s*PW_;

        #pragma unroll
        for (int kk = 0; kk < 4; kk++) {
            uint32_t a[2][4];
            #pragma unroll
            for (int mf = 0; mf < 2; mf++) {
                const int arow = mw*32 + mf*16 + (lane & 15);
                const int acol = kk*16 + (lane >> 4) * 8;
                ldm_x4(a[mf], xs + arow*72 + acol);
            }
            const int brow = kk*16 + (lane & 7) + ((lane >> 3) & 1) * 8;
            #pragma unroll
            for (int fp = 0; fp < 4; fp++) {
                uint32_t bb[4];
                const int bcol = nw*64 + fp*16 + ((lane >> 4) & 1) * 8;
                ldm_x4_t(bb, ws + brow*136 + bcol);
                #pragma unroll
                for (int mf = 0; mf < 2; mf++) {
                    mma16816(acc[mf][2*fp],   a[mf], &bb[0]);
                    mma16816(acc[mf][2*fp+1], a[mf], &bb[2]);
                }
            }
        }
        __syncthreads();
    }

    const float scale = (mat == 0) ? 0.08838834764831845f : 1.0f;
    #pragma unroll
    for (int mf = 0; mf < 2; mf++) {
        const int row0 = r0 + mw*32 + mf*16 + g;
        const int row1 = row0 + 8;
        #pragma unroll
        for (int f = 0; f < 8; f++) {
            const int col = nw*64 + f*8 + tg*2;
            *reinterpret_cast<uint32_t*>(op + (size_t)row0*H_ + col) =
                pack_h2(acc[mf][f][0]*scale, acc[mf][f][1]*scale);
            *reinterpret_cast<uint32_t*>(op + (size_t)row1*H_ + col) =
                pack_h2(acc[mf][f][2]*scale, acc[mf][f][3]*scale);
        }
    }
}

// ---------------------------------------------------------------------------
// Flash attention, split-KV(4): grid (4*T/64, B). Writes normalized fp16
// partial O plus (m, l) per row.
// ---------------------------------------------------------------------------
#define AT_ (64*136)

__global__ __launch_bounds__(128, 2) void attn_mma()
{
    extern __shared__ __half sma[];
    __half* Qs = sma;              // [64*136]
    __half* Ks = Qs + AT_;         // [2][64*136]
    __half* Vs = Ks + 2*AT_;       // [2][64*136]

    const int b    = blockIdx.y;
    const int nq   = (int)gridDim.x / NSPLIT;
    const int qi   = nq - 1 - ((int)blockIdx.x / NSPLIT);   // longest first
    const int p    = blockIdx.x % NSPLIT;
    const int q0   = qi * 64;
    const int ntile = qi + 1;
    const int j0   = (ntile * p) / NSPLIT;
    const int j1   = (ntile * (p + 1)) / NSPLIT;
    const int tid  = threadIdx.x;
    const int wrp  = tid >> 5;
    const int lane = tid & 31;
    const int g    = lane >> 2;
    const int tg   = lane & 3;

    float o[16][4];
    #pragma unroll
    for (int f = 0; f < 16; f++)
        #pragma unroll
        for (int e = 0; e < 4; e++) o[f][e] = 0.f;
    float m0 = -1e30f, m1 = -1e30f, l0 = 0.f, l1 = 0.f;

    auto issue_kv = [&](int j, int s) {
        const __half* kp = gk + (size_t)(b*T_ + j*64) * H_;
        const __half* vp = gv + (size_t)(b*T_ + j*64) * H_;
        #pragma unroll
        for (int it = 0; it < 8; it++) {
            int idx = it*128 + tid;
            int row = idx >> 4, u = idx & 15;
            int d = row*136 + u*8;
            size_t src = (size_t)row*H_ + u*8;
            cp16(Ks + s*AT_ + d, kp + src);
            cp16(Vs + s*AT_ + d, vp + src);
        }
        cp_commit();
    };

    if (j1 > j0) {
        // prologue: Q + KV stage j0
        {
            const __half* qp = gq + (size_t)(b*T_ + q0) * H_;
            #pragma unroll
            for (int it = 0; it < 8; it++) {
                int idx = it*128 + tid;
                int row = idx >> 4, u = idx & 15;
                cp16(Qs + row*136 + u*8, qp + (size_t)row*H_ + u*8);
            }
            const __half* kp = gk + (size_t)(b*T_ + j0*64) * H_;
            const __half* vp = gv + (size_t)(b*T_ + j0*64) * H_;
            #pragma unroll
            for (int it = 0; it < 8; it++) {
                int idx = it*128 + tid;
                int row = idx >> 4, u = idx & 15;
                int d = row*136 + u*8;
                size_t src = (size_t)row*H_ + u*8;
                cp16(Ks + d, kp + src);
                cp16(Vs + d, vp + src);
            }
            cp_commit();
        }

        for (int j = j0; j < j1; j++) {
            const int s = (j - j0) & 1;
            if (j + 1 < j1) { issue_kv(j+1, s^1); cp_wait<1>(); }
            else            { cp_wait<0>(); }
            __syncthreads();

            const __half* ks = Ks + s*AT_;
            const __half* vs = Vs + s*AT_;

            // ---- S = Q @ K^T ----
            float sv[8][4];
            #pragma unroll
            for (int f = 0; f < 8; f++)
                #pragma unroll
                for (int e = 0; e < 4; e++) sv[f][e] = 0.f;

            #pragma unroll
            for (int kk = 0; kk < 8; kk++) {
                uint32_t a[4];
                const int arow = 16*wrp + (lane & 15);
                const int acol = kk*16 + (lane >> 4) * 8;
                ldm_x4(a, Qs + arow*136 + acol);
                #pragma unroll
                for (int fp = 0; fp < 4; fp++) {
                    uint32_t bb[4];
                    const int brow = fp*16 + (lane & 7) + ((lane >> 4) & 1) * 8;
                    const int bcol = kk*16 + ((lane >> 3) & 1) * 8;
                    ldm_x4(bb, ks + brow*136 + bcol);
                    mma16816(sv[2*fp],   a, &bb[0]);
                    mma16816(sv[2*fp+1], a, &bb[2]);
                }
            }

            // ---- causal mask (diagonal tile) ----
            if (j == qi) {
                #pragma unroll
                for (int f = 0; f < 8; f++) {
                    #pragma unroll
                    for (int e = 0; e < 4; e++) {
                        int col = f*8 + tg*2 + (e & 1);
                        int row = wrp*16 + g + ((e >> 1) ? 8 : 0);
                        if (col > row) sv[f][e] = -1e30f;
                    }
                }
            }

            // ---- online softmax ----
            float rm0 = -1e30f, rm1 = -1e30f;
            #pragma unroll
            for (int f = 0; f < 8; f++) {
                rm0 = fmaxf(rm0, fmaxf(sv[f][0], sv[f][1]));
                rm1 = fmaxf(rm1, fmaxf(sv[f][2], sv[f][3]));
            }
            rm0 = fmaxf(rm0, __shfl_xor_sync(0xffffffffu, rm0, 1));
            rm0 = fmaxf(rm0, __shfl_xor_sync(0xffffffffu, rm0, 2));
            rm1 = fmaxf(rm1, __shfl_xor_sync(0xffffffffu, rm1, 1));
            rm1 = fmaxf(rm1, __shfl_xor_sync(0xffffffffu, rm1, 2));
            const float mn0 = fmaxf(m0, rm0), mn1 = fmaxf(m1, rm1);
            const float c0 = __expf(m0 - mn0), c1 = __expf(m1 - mn1);
            float ls0 = 0.f, ls1 = 0.f;
            #pragma unroll
            for (int f = 0; f < 8; f++) {
                sv[f][0] = __expf(sv[f][0] - mn0);
                sv[f][1] = __expf(sv[f][1] - mn0);
                sv[f][2] = __expf(sv[f][2] - mn1);
                sv[f][3] = __expf(sv[f][3] - mn1);
                ls0 += sv[f][0] + sv[f][1];
                ls1 += sv[f][2] + sv[f][3];
            }
            ls0 += __shfl_xor_sync(0xffffffffu, ls0, 1);
            ls0 += __shfl_xor_sync(0xffffffffu, ls0, 2);
            ls1 += __shfl_xor_sync(0xffffffffu, ls1, 1);
            ls1 += __shfl_xor_sync(0xffffffffu, ls1, 2);
            l0 = l0*c0 + ls0; l1 = l1*c1 + ls1;
            m0 = mn0; m1 = mn1;

            const bool noscale = (c0 == 1.0f) & (c1 == 1.0f);
            if (!__all_sync(0xffffffffu, noscale)) {
                #pragma unroll
                for (int f = 0; f < 16; f++) {
                    o[f][0] *= c0; o[f][1] *= c0;
                    o[f][2] *= c1; o[f][3] *= c1;
                }
            }

            // ---- O += P @ V ----
            #pragma unroll
            for (int kk = 0; kk < 4; kk++) {
                uint32_t a[4];
                a[0] = pack_h2(sv[2*kk][0],   sv[2*kk][1]);
                a[1] = pack_h2(sv[2*kk][2],   sv[2*kk][3]);
                a[2] = pack_h2(sv[2*kk+1][0], sv[2*kk+1][1]);
                a[3] = pack_h2(sv[2*kk+1][2], sv[2*kk+1][3]);
                const int brow = kk*16 + (lane & 7) + ((lane >> 3) & 1) * 8;
                #pragma unroll
                for (int fp = 0; fp < 8; fp++) {
                    uint32_t bb[4];
                    const int bcol = fp*16 + ((lane >> 4) & 1) * 8;
                    ldm_x4_t(bb, vs + brow*136 + bcol);
                    mma16816(o[2*fp],   a, &bb[0]);
                    mma16816(o[2*fp+1], a, &bb[2]);
                }
            }
            __syncthreads();
        }
    }

    // ---- epilogue: normalized fp16 partial O + (m, l) ----
    const float inv0 = (l0 > 0.f) ? 1.0f / l0 : 0.f;
    const float inv1 = (l1 > 0.f) ? 1.0f / l1 : 0.f;
    const size_t row0 = (size_t)b*T_ + q0 + wrp*16 + g;
    const size_t row1 = row0 + 8;
    __half* gop = goh[p];
    #pragma unroll
    for (int f = 0; f < 16; f++) {
        const int col = f*8 + tg*2;
        *reinterpret_cast<uint32_t*>(gop + row0*H_ + col) = pack_h2(o[f][0]*inv0, o[f][1]*inv0);
        *reinterpret_cast<uint32_t*>(gop + row1*H_ + col) = pack_h2(o[f][2]*inv1, o[f][3]*inv1);
    }
    if (tg == 0) {
        gm[p][row0] = m0; gl[p][row0] = l0;
        gm[p][row1] = m1; gl[p][row1] = l1;
    }
}

// ---------------------------------------------------------------------------
// Merge 4 normalized fp16 partials: out = sum_p w_p*Ohat_p / sum_p w_p,
// w_p = l_p * exp(m_p - m).
// ---------------------------------------------------------------------------
__global__ void merge_kernel(float* __restrict__ out)
{
    int i = blockIdx.x * 256 + threadIdx.x;     // float4 group over BT_*H_
    int row = i >> 5;
    float w[NSPLIT];
    float m = -1e30f;
    #pragma unroll
    for (int p = 0; p < NSPLIT; p++) m = fmaxf(m, gm[p][row]);
    float wsum = 0.f;
    #pragma unroll
    for (int p = 0; p < NSPLIT; p++) {
        w[p] = gl[p][row] * __expf(gm[p][row] - m);
        wsum += w[p];
    }
    float inv = 1.0f / wsum;
    float4 r = make_float4(0.f, 0.f, 0.f, 0.f);
    #pragma unroll
    for (int p = 0; p < NSPLIT; p++) {
        uint2 hv = reinterpret_cast<const uint2*>(goh[p])[i];
        __half2 h0 = *reinterpret_cast<__half2*>(&hv.x);
        __half2 h1 = *reinterpret_cast<__half2*>(&hv.y);
        float2 f0 = __half22float2(h0);
        float2 f1 = __half22float2(h1);
        r.x += f0.x * w[p];
        r.y += f0.y * w[p];
        r.z += f1.x * w[p];
        r.w += f1.y * w[p];
    }
    r.x *= inv; r.y *= inv; r.z *= inv; r.w *= inv;
    reinterpret_cast<float4*>(out)[i] = r;
}

extern "C" void kernel_launch(void* const* d_in, const int* in_sizes, int n_in,
                              void* d_out, int out_size)
{
    const float* x  = (const float*)d_in[0];
    const float* Wq = (const float*)d_in[1];
    const float* Wk = (const float*)d_in[2];
    const float* Wv = (const float*)d_in[3];
    float* out = (float*)d_out;

    const int proj_smem = (2*PX_ + 2*PW_) * (int)sizeof(__half);   // 71680
    const int attn_smem = 5*AT_ * (int)sizeof(__half);             // 87040
    cudaFuncSetAttribute(proj_mma, cudaFuncAttributeMaxDynamicSharedMemorySize, proj_smem);
    cudaFuncSetAttribute(attn_mma, cudaFuncAttributeMaxDynamicSharedMemorySize, attn_smem);

    conv_x_kernel<<<BT_*E_/4/256, 256>>>(x);
    conv_w_kernel<<<dim3(E_*H_/4/256, 3), 256>>>(Wq, Wk, Wv);
    proj_mma<<<dim3(BT_/128, 3), 256, proj_smem>>>();
    attn_mma<<<dim3(NSPLIT*T_/64, B_), 128, attn_smem>>>();
    merge_kernel<<<BT_*H_/4/256, 256>>>(out);
}

// round 15
// speedup vs baseline: 1.0521x; 1.0103x over previous
#include <cuda_runtime.h>
#include <cuda_fp16.h>
#include <stdint.h>

#define B_  8
#define T_  2048
#define E_  1024
#define H_  128
#define BT_ (B_*T_)
#define NSPLIT 4

// ---- global scratch ----
__device__ __half gw[3][E_*H_];
__device__ __half gq[BT_*H_];
__device__ __half gk[BT_*H_];
__device__ __half gv[BT_*H_];
__device__ __half goh[NSPLIT][BT_*H_];  // normalized partial O (fp16)
__device__ float  gm[NSPLIT][BT_];      // partial row max
__device__ float  gl[NSPLIT][BT_];      // partial row sum

// ---- helpers ----
__device__ __forceinline__ void ldm_x4(uint32_t* r, const void* p) {
    uint32_t a = (uint32_t)__cvta_generic_to_shared(p);
    asm volatile("ldmatrix.sync.aligned.m8n8.x4.shared.b16 {%0,%1,%2,%3}, [%4];"
                 : "=r"(r[0]), "=r"(r[1]), "=r"(r[2]), "=r"(r[3]) : "r"(a));
}
__device__ __forceinline__ void ldm_x4_t(uint32_t* r, const void* p) {
    uint32_t a = (uint32_t)__cvta_generic_to_shared(p);
    asm volatile("ldmatrix.sync.aligned.m8n8.x4.trans.shared.b16 {%0,%1,%2,%3}, [%4];"
                 : "=r"(r[0]), "=r"(r[1]), "=r"(r[2]), "=r"(r[3]) : "r"(a));
}
__device__ __forceinline__ void mma16816(float* d, const uint32_t* a, const uint32_t* b) {
    asm volatile("mma.sync.aligned.m16n8k16.row.col.f32.f16.f16.f32 "
                 "{%0,%1,%2,%3}, {%4,%5,%6,%7}, {%8,%9}, {%0,%1,%2,%3};"
                 : "+f"(d[0]), "+f"(d[1]), "+f"(d[2]), "+f"(d[3])
                 : "r"(a[0]), "r"(a[1]), "r"(a[2]), "r"(a[3]), "r"(b[0]), "r"(b[1]));
}
__device__ __forceinline__ uint32_t pack_h2(float a, float b) {
    __half2 h;
    h.x = __float2half_rn(a);
    h.y = __float2half_rn(b);
    return *reinterpret_cast<uint32_t*>(&h);
}
__device__ __forceinline__ void cp16(void* smem, const void* gmem) {
    uint32_t a = (uint32_t)__cvta_generic_to_shared(smem);
    asm volatile("cp.async.cg.shared.global [%0], [%1], 16;" :: "r"(a), "l"(gmem));
}
__device__ __forceinline__ void cp_commit() { asm volatile("cp.async.commit_group;"); }
template<int N> __device__ __forceinline__ void cp_wait() {
    asm volatile("cp.async.wait_group %0;" :: "n"(N));
}

// ---------------------------------------------------------------------------
// Convert W: fp32 -> fp16 (1.5 MB, trivial)
// ---------------------------------------------------------------------------
__global__ void conv_w_kernel(const float* __restrict__ Wq,
                              const float* __restrict__ Wk,
                              const float* __restrict__ Wv)
{
    const float* W = (blockIdx.y == 0) ? Wq : (blockIdx.y == 1) ? Wk : Wv;
    __half* o = gw[blockIdx.y];
    int i = blockIdx.x * 256 + threadIdx.x;
    float4 v = reinterpret_cast<const float4*>(W)[i];
    uint2 hv;
    hv.x = pack_h2(v.x, v.y);
    hv.y = pack_h2(v.z, v.w);
    reinterpret_cast<uint2*>(o)[i] = hv;
}

// ---------------------------------------------------------------------------
// Fused projection: CTA = 64 rows x 384 cols (q|k|v), 8 warps (16 x 192 each),
// BK=64. X: fp32 register-prefetch LDG -> cvt -> STS fp16 (double buffered).
// W: 2-stage cp.async of the 384-wide fp16 tile. Reads x exactly once.
// ---------------------------------------------------------------------------
#define PXF (64*72)     // fp16 X stage (64 rows x 72-padded)
#define PWF (64*392)    // fp16 W stage (64 k-rows x 392-padded 384 cols)

__global__ __launch_bounds__(256, 1) void proj_fused(const float* __restrict__ x)
{
    extern __shared__ __half smp[];
    __half* Xs = smp;               // [2][64*72]
    __half* Ws = Xs + 2*PXF;        // [2][64*392]

    const int r0   = blockIdx.x * 64;
    const int tid  = threadIdx.x;
    const int wrp  = tid >> 5;
    const int lane = tid & 31;
    const int mw   = wrp & 3;       // 16-row group
    const int nw   = wrp >> 2;      // 192-col group
    const int g    = lane >> 2;
    const int tg   = lane & 3;

    // X prefetch registers: 4 float4 per thread (64x64 fp32 tile).
    float4 xr[4];
    auto ldg_x = [&](int kc) {
        const int k0 = kc * 64;
        #pragma unroll
        for (int it = 0; it < 4; it++) {
            int idx = it*256 + tid;
            int row = idx >> 4, u = idx & 15;
            xr[it] = *reinterpret_cast<const float4*>(x + (size_t)(r0 + row) * E_ + k0 + u*4);
        }
    };
    auto sts_x = [&](int s) {
        #pragma unroll
        for (int it = 0; it < 4; it++) {
            int idx = it*256 + tid;
            int row = idx >> 4, u = idx & 15;
            uint2 hv;
            hv.x = pack_h2(xr[it].x, xr[it].y);
            hv.y = pack_h2(xr[it].z, xr[it].w);
            *reinterpret_cast<uint2*>(Xs + s*PXF + row*72 + u*4) = hv;
        }
    };
    auto issue_w = [&](int kc, int s) {
        const int k0 = kc * 64;
        #pragma unroll
        for (int it = 0; it < 12; it++) {
            int idx = it*256 + tid;
            int row = idx / 48, u = idx % 48;
            int mat = u >> 4, un = u & 15;
            cp16(Ws + s*PWF + row*392 + u*8,
                 gw[mat] + (size_t)(k0 + row) * H_ + un*8);
        }
        cp_commit();
    };

    float acc[24][4];
    #pragma unroll
    for (int f = 0; f < 24; f++)
        #pragma unroll
        for (int e = 0; e < 4; e++) acc[f][e] = 0.f;

    ldg_x(0);
    issue_w(0, 0);

    for (int kc = 0; kc < 16; kc++) {
        const int s = kc & 1;
        sts_x(s);                               // consume xr (chunk kc)
        if (kc < 15) {
            issue_w(kc+1, s^1);
            ldg_x(kc+1);                        // hidden under this chunk's MMAs
            cp_wait<1>();
        } else {
            cp_wait<0>();
        }
        __syncthreads();

        const __half* xs = Xs + s*PXF;
        const __half* ws = Ws + s*PWF;

        #pragma unroll
        for (int kk = 0; kk < 4; kk++) {
            uint32_t a[4];
            const int arow = mw*16 + (lane & 15);
            const int acol = kk*16 + (lane >> 4) * 8;
            ldm_x4(a, xs + arow*72 + acol);
            const int brow = kk*16 + (lane & 7) + ((lane >> 3) & 1) * 8;
            #pragma unroll
            for (int fp = 0; fp < 12; fp++) {
                uint32_t bb[4];
                const int bcol = nw*192 + fp*16 + ((lane >> 4) & 1) * 8;
                ldm_x4_t(bb, ws + brow*392 + bcol);
                mma16816(acc[2*fp],   a, &bb[0]);
                mma16816(acc[2*fp+1], a, &bb[2]);
            }
        }
        __syncthreads();
    }

    // Epilogue: map column -> (matrix, local col); q gets 1/sqrt(H) scale.
    const int row0 = r0 + mw*16 + g;
    const int row1 = row0 + 8;
    #pragma unroll
    for (int f = 0; f < 24; f++) {
        const int col = nw*192 + f*8 + tg*2;
        const int mat = col >> 7;
        const int cm  = col & 127;
        __half* op = (mat == 0) ? gq : (mat == 1) ? gk : gv;
        const float sc = (mat == 0) ? 0.08838834764831845f : 1.0f;
        *reinterpret_cast<uint32_t*>(op + (size_t)row0*H_ + cm) =
            pack_h2(acc[f][0]*sc, acc[f][1]*sc);
        *reinterpret_cast<uint32_t*>(op + (size_t)row1*H_ + cm) =
            pack_h2(acc[f][2]*sc, acc[f][3]*sc);
    }
}

// ---------------------------------------------------------------------------
// Flash attention, split-KV(4): grid (4*T/64, B). Writes normalized fp16
// partial O plus (m, l) per row. (Unchanged from R14.)
// ---------------------------------------------------------------------------
#define AT_ (64*136)

__global__ __launch_bounds__(128, 2) void attn_mma()
{
    extern __shared__ __half sma[];
    __half* Qs = sma;              // [64*136]
    __half* Ks = Qs + AT_;         // [2][64*136]
    __half* Vs = Ks + 2*AT_;       // [2][64*136]

    const int b    = blockIdx.y;
    const int nq   = (int)gridDim.x / NSPLIT;
    const int qi   = nq - 1 - ((int)blockIdx.x / NSPLIT);   // longest first
    const int p    = blockIdx.x % NSPLIT;
    const int q0   = qi * 64;
    const int ntile = qi + 1;
    const int j0   = (ntile * p) / NSPLIT;
    const int j1   = (ntile * (p + 1)) / NSPLIT;
    const int tid  = threadIdx.x;
    const int wrp  = tid >> 5;
    const int lane = tid & 31;
    const int g    = lane >> 2;
    const int tg   = lane & 3;

    float o[16][4];
    #pragma unroll
    for (int f = 0; f < 16; f++)
        #pragma unroll
        for (int e = 0; e < 4; e++) o[f][e] = 0.f;
    float m0 = -1e30f, m1 = -1e30f, l0 = 0.f, l1 = 0.f;

    auto issue_kv = [&](int j, int s) {
        const __half* kp = gk + (size_t)(b*T_ + j*64) * H_;
        const __half* vp = gv + (size_t)(b*T_ + j*64) * H_;
        #pragma unroll
        for (int it = 0; it < 8; it++) {
            int idx = it*128 + tid;
            int row = idx >> 4, u = idx & 15;
            int d = row*136 + u*8;
            size_t src = (size_t)row*H_ + u*8;
            cp16(Ks + s*AT_ + d, kp + src);
            cp16(Vs + s*AT_ + d, vp + src);
        }
        cp_commit();
    };

    if (j1 > j0) {
        {
            const __half* qp = gq + (size_t)(b*T_ + q0) * H_;
            #pragma unroll
            for (int it = 0; it < 8; it++) {
                int idx = it*128 + tid;
                int row = idx >> 4, u = idx & 15;
                cp16(Qs + row*136 + u*8, qp + (size_t)row*H_ + u*8);
            }
            const __half* kp = gk + (size_t)(b*T_ + j0*64) * H_;
            const __half* vp = gv + (size_t)(b*T_ + j0*64) * H_;
            #pragma unroll
            for (int it = 0; it < 8; it++) {
                int idx = it*128 + tid;
                int row = idx >> 4, u = idx & 15;
                int d = row*136 + u*8;
                size_t src = (size_t)row*H_ + u*8;
                cp16(Ks + d, kp + src);
                cp16(Vs + d, vp + src);
            }
            cp_commit();
        }

        for (int j = j0; j < j1; j++) {
            const int s = (j - j0) & 1;
            if (j + 1 < j1) { issue_kv(j+1, s^1); cp_wait<1>(); }
            else            { cp_wait<0>(); }
            __syncthreads();

            const __half* ks = Ks + s*AT_;
            const __half* vs = Vs + s*AT_;

            float sv[8][4];
            #pragma unroll
            for (int f = 0; f < 8; f++)
                #pragma unroll
                for (int e = 0; e < 4; e++) sv[f][e] = 0.f;

            #pragma unroll
            for (int kk = 0; kk < 8; kk++) {
                uint32_t a[4];
                const int arow = 16*wrp + (lane & 15);
                const int acol = kk*16 + (lane >> 4) * 8;
                ldm_x4(a, Qs + arow*136 + acol);
                #pragma unroll
                for (int fp = 0; fp < 4; fp++) {
                    uint32_t bb[4];
                    const int brow = fp*16 + (lane & 7) + ((lane >> 4) & 1) * 8;
                    const int bcol = kk*16 + ((lane >> 3) & 1) * 8;
                    ldm_x4(bb, ks + brow*136 + bcol);
                    mma16816(sv[2*fp],   a, &bb[0]);
                    mma16816(sv[2*fp+1], a, &bb[2]);
                }
            }

            if (j == qi) {
                #pragma unroll
                for (int f = 0; f < 8; f++) {
                    #pragma unroll
                    for (int e = 0; e < 4; e++) {
                        int col = f*8 + tg*2 + (e & 1);
                        int row = wrp*16 + g + ((e >> 1) ? 8 : 0);
                        if (col > row) sv[f][e] = -1e30f;
                    }
                }
            }

            float rm0 = -1e30f, rm1 = -1e30f;
            #pragma unroll
            for (int f = 0; f < 8; f++) {
                rm0 = fmaxf(rm0, fmaxf(sv[f][0], sv[f][1]));
                rm1 = fmaxf(rm1, fmaxf(sv[f][2], sv[f][3]));
            }
            rm0 = fmaxf(rm0, __shfl_xor_sync(0xffffffffu, rm0, 1));
            rm0 = fmaxf(rm0, __shfl_xor_sync(0xffffffffu, rm0, 2));
            rm1 = fmaxf(rm1, __shfl_xor_sync(0xffffffffu, rm1, 1));
            rm1 = fmaxf(rm1, __shfl_xor_sync(0xffffffffu, rm1, 2));
            const float mn0 = fmaxf(m0, rm0), mn1 = fmaxf(m1, rm1);
            const float c0 = __expf(m0 - mn0), c1 = __expf(m1 - mn1);
            float ls0 = 0.f, ls1 = 0.f;
            #pragma unroll
            for (int f = 0; f < 8; f++) {
                sv[f][0] = __expf(sv[f][0] - mn0);
                sv[f][1] = __expf(sv[f][1] - mn0);
                sv[f][2] = __expf(sv[f][2] - mn1);
                sv[f][3] = __expf(sv[f][3] - mn1);
                ls0 += sv[f][0] + sv[f][1];
                ls1 += sv[f][2] + sv[f][3];
            }
            ls0 += __shfl_xor_sync(0xffffffffu, ls0, 1);
            ls0 += __shfl_xor_sync(0xffffffffu, ls0, 2);
            ls1 += __shfl_xor_sync(0xffffffffu, ls1, 1);
            ls1 += __shfl_xor_sync(0xffffffffu, ls1, 2);
            l0 = l0*c0 + ls0; l1 = l1*c1 + ls1;
            m0 = mn0; m1 = mn1;

            const bool noscale = (c0 == 1.0f) & (c1 == 1.0f);
            if (!__all_sync(0xffffffffu, noscale)) {
                #pragma unroll
                for (int f = 0; f < 16; f++) {
                    o[f][0] *= c0; o[f][1] *= c0;
                    o[f][2] *= c1; o[f][3] *= c1;
                }
            }

            #pragma unroll
            for (int kk = 0; kk < 4; kk++) {
                uint32_t a[4];
                a[0] = pack_h2(sv[2*kk][0],   sv[2*kk][1]);
                a[1] = pack_h2(sv[2*kk][2],   sv[2*kk][3]);
                a[2] = pack_h2(sv[2*kk+1][0], sv[2*kk+1][1]);
                a[3] = pack_h2(sv[2*kk+1][2], sv[2*kk+1][3]);
                const int brow = kk*16 + (lane & 7) + ((lane >> 3) & 1) * 8;
                #pragma unroll
                for (int fp = 0; fp < 8; fp++) {
                    uint32_t bb[4];
                    const int bcol = fp*16 + ((lane >> 4) & 1) * 8;
                    ldm_x4_t(bb, vs + brow*136 + bcol);
                    mma16816(o[2*fp],   a, &bb[0]);
                    mma16816(o[2*fp+1], a, &bb[2]);
                }
            }
            __syncthreads();
        }
    }

    const float inv0 = (l0 > 0.f) ? 1.0f / l0 : 0.f;
    const float inv1 = (l1 > 0.f) ? 1.0f / l1 : 0.f;
    const size_t row0 = (size_t)b*T_ + q0 + wrp*16 + g;
    const size_t row1 = row0 + 8;
    __half* gop = goh[p];
    #pragma unroll
    for (int f = 0; f < 16; f++) {
        const int col = f*8 + tg*2;
        *reinterpret_cast<uint32_t*>(gop + row0*H_ + col) = pack_h2(o[f][0]*inv0, o[f][1]*inv0);
        *reinterpret_cast<uint32_t*>(gop + row1*H_ + col) = pack_h2(o[f][2]*inv1, o[f][3]*inv1);
    }
    if (tg == 0) {
        gm[p][row0] = m0; gl[p][row0] = l0;
        gm[p][row1] = m1; gl[p][row1] = l1;
    }
}

// ---------------------------------------------------------------------------
// Merge 4 normalized fp16 partials.
// ---------------------------------------------------------------------------
__global__ void merge_kernel(float* __restrict__ out)
{
    int i = blockIdx.x * 256 + threadIdx.x;
    int row = i >> 5;
    float w[NSPLIT];
    float m = -1e30f;
    #pragma unroll
    for (int p = 0; p < NSPLIT; p++) m = fmaxf(m, gm[p][row]);
    float wsum = 0.f;
    #pragma unroll
    for (int p = 0; p < NSPLIT; p++) {
        w[p] = gl[p][row] * __expf(gm[p][row] - m);
        wsum += w[p];
    }
    float inv = 1.0f / wsum;
    float4 r = make_float4(0.f, 0.f, 0.f, 0.f);
    #pragma unroll
    for (int p = 0; p < NSPLIT; p++) {
        uint2 hv = reinterpret_cast<const uint2*>(goh[p])[i];
        __half2 h0 = *reinterpret_cast<__half2*>(&hv.x);
        __half2 h1 = *reinterpret_cast<__half2*>(&hv.y);
        float2 f0 = __half22float2(h0);
        float2 f1 = __half22float2(h1);
        r.x += f0.x * w[p];
        r.y += f0.y * w[p];
        r.z += f1.x * w[p];
        r.w += f1.y * w[p];
    }
    r.x *= inv; r.y *= inv; r.z *= inv; r.w *= inv;
    reinterpret_cast<float4*>(out)[i] = r;
}

extern "C" void kernel_launch(void* const* d_in, const int* in_sizes, int n_in,
                              void* d_out, int out_size)
{
    const float* x  = (const float*)d_in[0];
    const float* Wq = (const float*)d_in[1];
    const float* Wk = (const float*)d_in[2];
    const float* Wv = (const float*)d_in[3];
    float* out = (float*)d_out;

    const int proj_smem = (2*PXF + 2*PWF) * (int)sizeof(__half);   // 118784
    const int attn_smem = 5*AT_ * (int)sizeof(__half);             // 87040
    cudaFuncSetAttribute(proj_fused, cudaFuncAttributeMaxDynamicSharedMemorySize, proj_smem);
    cudaFuncSetAttribute(attn_mma,   cudaFuncAttributeMaxDynamicSharedMemorySize, attn_smem);

    conv_w_kernel<<<dim3(E_*H_/4/256, 3), 256>>>(Wq, Wk, Wv);
    proj_fused<<<BT_/64, 256, proj_smem>>>(x);
    attn_mma<<<dim3(NSPLIT*T_/64, B_), 128, attn_smem>>>();
    merge_kernel<<<BT_*H_/4/256, 256>>>(out);
}